// round 5
// baseline (speedup 1.0000x reference)
#include <cuda_runtime.h>
#include <stdint.h>

// Binarized depthwise 3x3 conv, stride 1, SAME. x:(16,112,112,256) NHWC fp32,
// kernel:(3,3,256,1). out = sum of sign(x)*sign(k) over valid taps.
//
// bf16x2 math: pack 2 channels' fp32 high-halves into one reg (PRMT); per tap
// one LOP3 ((t & 0x80008000) ^ kp) yields bf16x2 of +-1.0 (or +-0.0 when kp
// is zeroed for a missing border row); accumulate with add.rn.bf16x2 (exact,
// |sum| <= 9). Streaming column recurrence:
//   out[c-1] = A + q2(c); A = B + q1(c); B = q0(c)
//
// PERSISTENT CTAs + ATOMIC WORK QUEUE: grid == resident CTA count; units are
// (n, h, W-half) popped from a global counter. Eliminates the ~1.05-wave
// quantization tail where leftover CTAs ran alone at latency-bound bandwidth.

#define NN 16
#define HH 112
#define WW 112
#define CC 256
#define NUNITS (NN * HH * 2)   // 3584 half-row units

__device__ int g_unit_counter;

__global__ void reset_counter_kernel() { g_unit_counter = 0; }

__device__ __forceinline__ uint32_t badd(uint32_t a, uint32_t b) {
    uint32_t r;
    asm("add.rn.bf16x2 %0, %1, %2;" : "=r"(r) : "r"(a), "r"(b));
    return r;
}

#define TAPP(t, kp) ((((t) & 0x80008000u)) ^ (kp))

__device__ __forceinline__ uint32_t pack2(float2 v) {
    return __byte_perm(__float_as_uint(v.x), __float_as_uint(v.y), 0x7632);
}

__global__ __launch_bounds__(128, 12)
void bconv_kernel(const float* __restrict__ x,
                  const float* __restrict__ k,
                  float* __restrict__ out) {
    const int t = threadIdx.x;          // channel pair 0..127
    const int c0 = t * 2;
    __shared__ int s_unit;

    // Base kernel signs as bf16x2 of +-1.0 per channel pair (loaded once).
    uint32_t kpb[3][3];
#pragma unroll
    for (int kh = 0; kh < 3; ++kh)
#pragma unroll
        for (int kw = 0; kw < 3; ++kw) {
            const float2 kv = *reinterpret_cast<const float2*>(k + (kh * 3 + kw) * CC + c0);
            uint32_t s0 = (kv.x >= 0.0f) ? 0x3F80u : 0xBF80u;
            uint32_t s1 = (kv.y >= 0.0f) ? 0x3F80u : 0xBF80u;
            kpb[kh][kw] = s0 | (s1 << 16);
        }

    for (;;) {
        __syncthreads();                          // protect s_unit reuse
        if (t == 0) s_unit = atomicAdd(&g_unit_counter, 1);
        __syncthreads();
        const int u = s_unit;
        if (u >= NUNITS) return;                  // uniform exit

        const int n = u / (HH * 2);
        const int rem = u - n * (HH * 2);
        const int h = rem >> 1;
        const int strip = rem & 1;

        const bool hasT = (h > 0);
        const bool hasB = (h < HH - 1);
        uint32_t kp0[3], kp2[3];
#pragma unroll
        for (int kw = 0; kw < 3; ++kw) {
            kp0[kw] = hasT ? kpb[0][kw] : 0u;     // zeroed taps add +-0.0
            kp2[kw] = hasB ? kpb[2][kw] : 0u;
        }

        const int hm = hasT ? h - 1 : h;          // clamped; zeroed via kp
        const int hp = hasB ? h + 1 : h;
        const float* r0 = x + (((size_t)n * HH + hm) * WW) * CC + c0;
        const float* r1 = x + (((size_t)n * HH + h ) * WW) * CC + c0;
        const float* r2 = x + (((size_t)n * HH + hp) * WW) * CC + c0;
        float*       o  = out + (((size_t)n * HH + h) * WW) * CC + c0;

        const int ws = strip * (WW / 2);
        const int we = ws + (WW / 2);
        const int cbeg = (ws == 0) ? 0 : ws - 1;
        const int cend = (we == WW) ? WW - 1 : we;

        uint32_t A = 0, B = 0;

#pragma unroll 4
        for (int c = cbeg; c <= cend; ++c) {
            const uint32_t t0 = pack2(*reinterpret_cast<const float2*>(r0 + (size_t)c * CC));
            const uint32_t t1 = pack2(*reinterpret_cast<const float2*>(r1 + (size_t)c * CC));
            const uint32_t t2 = pack2(*reinterpret_cast<const float2*>(r2 + (size_t)c * CC));

            const uint32_t q0 = badd(badd(TAPP(t0, kp0[0]), TAPP(t1, kpb[1][0])), TAPP(t2, kp2[0]));
            const uint32_t q1 = badd(badd(TAPP(t0, kp0[1]), TAPP(t1, kpb[1][1])), TAPP(t2, kp2[1]));
            const uint32_t q2 = badd(badd(TAPP(t0, kp0[2]), TAPP(t1, kpb[1][2])), TAPP(t2, kp2[2]));

            if (c > ws) {  // completes out[c-1] (uniform predicate)
                const uint32_t ov = badd(A, q2);
                float2 o2;
                o2.x = __uint_as_float(ov << 16);
                o2.y = __uint_as_float(ov & 0xFFFF0000u);
                __stcs(reinterpret_cast<float2*>(o + (size_t)(c - 1) * CC), o2);
            }
            A = badd(B, q1);
            B = q0;
        }

        if (we == WW) {  // right border: out[111] = q0(110) + q1(111) = A
            float2 o2;
            o2.x = __uint_as_float(A << 16);
            o2.y = __uint_as_float(A & 0xFFFF0000u);
            __stcs(reinterpret_cast<float2*>(o + (size_t)(WW - 1) * CC), o2);
        }
    }
}

extern "C" void kernel_launch(void* const* d_in, const int* in_sizes, int n_in,
                              void* d_out, int out_size) {
    const float* x = (const float*)d_in[0];
    const float* k = (const float*)d_in[1];
    float* out = (float*)d_out;

    int dev = 0;
    cudaGetDevice(&dev);
    int sms = 148;
    cudaDeviceGetAttribute(&sms, cudaDevAttrMultiProcessorCount, dev);
    int bpm = 1;
    cudaOccupancyMaxActiveBlocksPerMultiprocessor(&bpm, bconv_kernel, 128, 0);
    int grid = sms * bpm;
    if (grid > NUNITS) grid = NUNITS;
    if (grid < 1) grid = 1;

    reset_counter_kernel<<<1, 1>>>();
    bconv_kernel<<<grid, 128>>>(x, k, out);
}

// round 6
// speedup vs baseline: 1.1042x; 1.1042x over previous
#include <cuda_runtime.h>
#include <stdint.h>

// Binarized depthwise 3x3 conv, stride 1, SAME. x:(16,112,112,256) NHWC fp32,
// kernel:(3,3,256,1). out = sum of sign(x)*sign(k) over valid taps.
//
// bf16x2 math: pack 2 channels' fp32 high-halves into one reg (PRMT); per tap
// one LOP3 ((t & 0x80008000) ^ kp) yields bf16x2 of +-1.0 (or +-0.0 when kp
// is zeroed for a missing border row); accumulate with add.rn.bf16x2 (exact,
// |sum| <= 9). Streaming column recurrence per output row:
//   out[c-1] = A + q2(c); A = B + q1(c); B = q0(c)
//
// ROW PAIRING (L2-cap relief): each thread computes 2 adjacent output rows
// from 4 input rows -> input passes through L2 2x instead of 3x (R3 measured
// 11.8 TB/s L2 == the B300 LTS cap; this drops it to ~9 TB/s).
// Register diet for occupancy: r2/oB addressed as r1/oA + constant row
// stride (folded into LDG/STG immediates), launch_bounds(128,10).

#define NN 16
#define HH 112
#define WW 112
#define CC 256
#define RS (WW * CC)            // row stride in elements (114688 B)

__device__ __forceinline__ uint32_t badd(uint32_t a, uint32_t b) {
    uint32_t r;
    asm("add.rn.bf16x2 %0, %1, %2;" : "=r"(r) : "r"(a), "r"(b));
    return r;
}

#define TAPP(t, kp) ((((t) & 0x80008000u)) ^ (kp))

__device__ __forceinline__ uint32_t pack2(const float* __restrict__ p) {
    const float2 v = *reinterpret_cast<const float2*>(p);
    return __byte_perm(__float_as_uint(v.x), __float_as_uint(v.y), 0x7632);
}

__device__ __forceinline__ void store2(float* __restrict__ p, uint32_t ov) {
    float2 o2;
    o2.x = __uint_as_float(ov << 16);
    o2.y = __uint_as_float(ov & 0xFFFF0000u);
    *reinterpret_cast<float2*>(p) = o2;
}

__global__ __launch_bounds__(128, 10)
void bconv_kernel(const float* __restrict__ x,
                  const float* __restrict__ k,
                  float* __restrict__ out) {
    const int hpair = blockIdx.x >> 2;      // 0..55 -> output rows 2i, 2i+1
    const int strip = blockIdx.x & 3;       // 4 strips of 28 columns
    const int n = blockIdx.y;
    const int t = threadIdx.x;              // channel pair 0..127
    const int c0 = t * 2;

    const int h0 = hpair * 2;
    const bool hasT = (hpair != 0);
    const bool hasB = (hpair != 55);

    // Kernel signs as bf16x2 of +-1.0 per channel pair.
    uint32_t kp[3][3];
#pragma unroll
    for (int kh = 0; kh < 3; ++kh)
#pragma unroll
        for (int kw = 0; kw < 3; ++kw) {
            const float2 kv = *reinterpret_cast<const float2*>(k + (kh * 3 + kw) * CC + c0);
            uint32_t s0 = (kv.x >= 0.0f) ? 0x3F80u : 0xBF80u;
            uint32_t s1 = (kv.y >= 0.0f) ? 0x3F80u : 0xBF80u;
            kp[kh][kw] = s0 | (s1 << 16);
        }
    // Border-zeroed outer taps (zeroed kp -> adds +-0.0, a no-op).
    uint32_t kpA0[3], kpB2[3];
#pragma unroll
    for (int kw = 0; kw < 3; ++kw) {
        kpA0[kw] = hasT ? kp[0][kw] : 0u;
        kpB2[kw] = hasB ? kp[2][kw] : 0u;
    }

    // Pointers: r1 = row h0; r2 = r1 + RS (constant offset). r0/r3 dynamic
    // (clamped to a valid row when missing; contribution zeroed via kp).
    const float* r1 = x + (((size_t)n * HH + h0) * WW) * CC + c0;
    const float* r0 = hasT ? r1 - RS : r1;
    const float* r3 = hasB ? r1 + 2 * RS : r1;
    float*       oA = out + (((size_t)n * HH + h0) * WW) * CC + c0;

    const int ws = strip * (WW / 4);
    const int we = ws + (WW / 4);
    const int cbeg = (ws == 0) ? 0 : ws - 1;
    const int cend = (we == WW) ? WW - 1 : we;

    uint32_t AA = 0, BA = 0, AB = 0, BB = 0;

#pragma unroll 2
    for (int c = cbeg; c <= cend; ++c) {
        const size_t cc = (size_t)c * CC;
        const uint32_t t0 = pack2(r0 + cc);
        const uint32_t t1 = pack2(r1 + cc);
        const uint32_t t2 = pack2(r1 + cc + RS);   // row h0+1 (always valid)
        const uint32_t t3 = pack2(r3 + cc);

        // Row A (h0): rows (t0,t1,t2) vs kh (0,1,2); top tap may be zeroed.
        const uint32_t qA0 = badd(badd(TAPP(t0, kpA0[0]), TAPP(t1, kp[1][0])), TAPP(t2, kp[2][0]));
        const uint32_t qA1 = badd(badd(TAPP(t0, kpA0[1]), TAPP(t1, kp[1][1])), TAPP(t2, kp[2][1]));
        const uint32_t qA2 = badd(badd(TAPP(t0, kpA0[2]), TAPP(t1, kp[1][2])), TAPP(t2, kp[2][2]));
        // Row B (h0+1): rows (t1,t2,t3) vs kh (0,1,2); bottom tap may be zeroed.
        const uint32_t qB0 = badd(badd(TAPP(t1, kp[0][0]), TAPP(t2, kp[1][0])), TAPP(t3, kpB2[0]));
        const uint32_t qB1 = badd(badd(TAPP(t1, kp[0][1]), TAPP(t2, kp[1][1])), TAPP(t3, kpB2[1]));
        const uint32_t qB2 = badd(badd(TAPP(t1, kp[0][2]), TAPP(t2, kp[1][2])), TAPP(t3, kpB2[2]));

        if (c > ws) {  // completes out[c-1] (uniform predicate)
            const size_t po = (size_t)(c - 1) * CC;
            store2(oA + po,      badd(AA, qA2));
            store2(oA + po + RS, badd(AB, qB2));
        }
        AA = badd(BA, qA1); BA = qA0;
        AB = badd(BB, qB1); BB = qB0;
    }

    if (we == WW) {  // right border: out[111] = q0(110) + q1(111) = A
        const size_t po = (size_t)(WW - 1) * CC;
        store2(oA + po,      AA);
        store2(oA + po + RS, AB);
    }
}

extern "C" void kernel_launch(void* const* d_in, const int* in_sizes, int n_in,
                              void* d_out, int out_size) {
    const float* x = (const float*)d_in[0];
    const float* k = (const float*)d_in[1];
    float* out = (float*)d_out;
    dim3 grid(224, NN);   // 224 = 56 row-pairs x 4 strips
    bconv_kernel<<<grid, 128>>>(x, k, out);
}

// round 7
// speedup vs baseline: 1.1101x; 1.0053x over previous
#include <cuda_runtime.h>
#include <stdint.h>

// Binarized depthwise 3x3 conv, stride 1, SAME. x:(16,112,112,256) NHWC fp32,
// kernel:(3,3,256,1). out = sum of sign(x)*sign(k) over valid taps.
//
// bf16x2 math: pack 2 channels' fp32 high-halves into one reg (PRMT); per tap
// one LOP3 ((t & 0x80008000) ^ kp) yields bf16x2 of +-1.0 (or +-0.0 when kp
// is zeroed for a missing border row); accumulate with add.rn.bf16x2 (exact,
// |sum| <= 9). Streaming column recurrence per output row:
//   out[c-1] = A + q2(c); A = B + q1(c); B = q0(c)
//
// Row pairing: 2 output rows per thread from 4 input rows (2x L2 amp).
// This round: branchless inner loop (first column peeled so the store
// predicate disappears) + unroll 4 so ~16 LDGs front-batch per warp (MLP),
// since R2-R6 showed nothing saturated -> latency/concurrency bound.

#define NN 16
#define HH 112
#define WW 112
#define CC 256
#define RS (WW * CC)            // row stride in elements

__device__ __forceinline__ uint32_t badd(uint32_t a, uint32_t b) {
    uint32_t r;
    asm("add.rn.bf16x2 %0, %1, %2;" : "=r"(r) : "r"(a), "r"(b));
    return r;
}

#define TAPP(t, kp) ((((t) & 0x80008000u)) ^ (kp))

__device__ __forceinline__ uint32_t pack2(const float* __restrict__ p) {
    const float2 v = *reinterpret_cast<const float2*>(p);
    return __byte_perm(__float_as_uint(v.x), __float_as_uint(v.y), 0x7632);
}

__device__ __forceinline__ void store2(float* __restrict__ p, uint32_t ov) {
    float2 o2;
    o2.x = __uint_as_float(ov << 16);
    o2.y = __uint_as_float(ov & 0xFFFF0000u);
    *reinterpret_cast<float2*>(p) = o2;
}

__global__ __launch_bounds__(128, 8)
void bconv_kernel(const float* __restrict__ x,
                  const float* __restrict__ k,
                  float* __restrict__ out) {
    const int hpair = blockIdx.x >> 2;      // 0..55 -> output rows 2i, 2i+1
    const int strip = blockIdx.x & 3;       // 4 strips of 28 columns
    const int n = blockIdx.y;
    const int t = threadIdx.x;              // channel pair 0..127
    const int c0 = t * 2;

    const int h0 = hpair * 2;
    const bool hasT = (hpair != 0);
    const bool hasB = (hpair != 55);

    // Kernel signs as bf16x2 of +-1.0 per channel pair.
    uint32_t kp[3][3];
#pragma unroll
    for (int kh = 0; kh < 3; ++kh)
#pragma unroll
        for (int kw = 0; kw < 3; ++kw) {
            const float2 kv = *reinterpret_cast<const float2*>(k + (kh * 3 + kw) * CC + c0);
            uint32_t s0 = (kv.x >= 0.0f) ? 0x3F80u : 0xBF80u;
            uint32_t s1 = (kv.y >= 0.0f) ? 0x3F80u : 0xBF80u;
            kp[kh][kw] = s0 | (s1 << 16);
        }
    // Border-zeroed outer taps (zeroed kp -> adds +-0.0, a no-op).
    uint32_t kpA0[3], kpB2[3];
#pragma unroll
    for (int kw = 0; kw < 3; ++kw) {
        kpA0[kw] = hasT ? kp[0][kw] : 0u;
        kpB2[kw] = hasB ? kp[2][kw] : 0u;
    }

    const float* r1 = x + (((size_t)n * HH + h0) * WW) * CC + c0;   // row h0
    const float* r0 = hasT ? r1 - RS : r1;                          // clamped
    const float* r3 = hasB ? r1 + 2 * RS : r1;                      // clamped
    float*       oA = out + (((size_t)n * HH + h0) * WW) * CC + c0;

    const int ws = strip * (WW / 4);
    const int we = ws + (WW / 4);
    const int cbeg = (ws == 0) ? 0 : ws - 1;
    const int cend = (we == WW) ? WW - 1 : we;

    uint32_t AA, BA, AB, BB;

    // ---- peeled first column (no store) ----
    {
        const size_t cc = (size_t)cbeg * CC;
        const uint32_t t0 = pack2(r0 + cc);
        const uint32_t t1 = pack2(r1 + cc);
        const uint32_t t2 = pack2(r1 + cc + RS);
        const uint32_t t3 = pack2(r3 + cc);
        BA = badd(badd(TAPP(t0, kpA0[0]), TAPP(t1, kp[1][0])), TAPP(t2, kp[2][0]));
        AA = badd(badd(TAPP(t0, kpA0[1]), TAPP(t1, kp[1][1])), TAPP(t2, kp[2][1]));
        BB = badd(badd(TAPP(t1, kp[0][0]), TAPP(t2, kp[1][0])), TAPP(t3, kpB2[0]));
        AB = badd(badd(TAPP(t1, kp[0][1]), TAPP(t2, kp[1][1])), TAPP(t3, kpB2[1]));
    }

    // ---- branchless main loop: load col c, store col c-1 ----
#pragma unroll 4
    for (int c = cbeg + 1; c <= cend; ++c) {
        const size_t cc = (size_t)c * CC;
        const uint32_t t0 = pack2(r0 + cc);
        const uint32_t t1 = pack2(r1 + cc);
        const uint32_t t2 = pack2(r1 + cc + RS);
        const uint32_t t3 = pack2(r3 + cc);

        const uint32_t qA0 = badd(badd(TAPP(t0, kpA0[0]), TAPP(t1, kp[1][0])), TAPP(t2, kp[2][0]));
        const uint32_t qA1 = badd(badd(TAPP(t0, kpA0[1]), TAPP(t1, kp[1][1])), TAPP(t2, kp[2][1]));
        const uint32_t qA2 = badd(badd(TAPP(t0, kpA0[2]), TAPP(t1, kp[1][2])), TAPP(t2, kp[2][2]));
        const uint32_t qB0 = badd(badd(TAPP(t1, kp[0][0]), TAPP(t2, kp[1][0])), TAPP(t3, kpB2[0]));
        const uint32_t qB1 = badd(badd(TAPP(t1, kp[0][1]), TAPP(t2, kp[1][1])), TAPP(t3, kpB2[1]));
        const uint32_t qB2 = badd(badd(TAPP(t1, kp[0][2]), TAPP(t2, kp[1][2])), TAPP(t3, kpB2[2]));

        const size_t po = (size_t)(c - 1) * CC;
        store2(oA + po,      badd(AA, qA2));
        store2(oA + po + RS, badd(AB, qB2));

        AA = badd(BA, qA1); BA = qA0;
        AB = badd(BB, qB1); BB = qB0;
    }

    if (we == WW) {  // right border: out[111] = q0(110) + q1(111) = A
        const size_t po = (size_t)(WW - 1) * CC;
        store2(oA + po,      AA);
        store2(oA + po + RS, AB);
    }
}

extern "C" void kernel_launch(void* const* d_in, const int* in_sizes, int n_in,
                              void* d_out, int out_size) {
    const float* x = (const float*)d_in[0];
    const float* k = (const float*)d_in[1];
    float* out = (float*)d_out;
    dim3 grid(224, NN);   // 224 = 56 row-pairs x 4 strips
    bconv_kernel<<<grid, 128>>>(x, k, out);
}